// round 2
// baseline (speedup 1.0000x reference)
#include <cuda_runtime.h>

#define N_NODES 50000
#define N_EDGES 800000
#define FEATS   512
#define N_ELEMS (N_NODES * FEATS)          // 25,600,000

// Scratch (device globals — no cudaMalloc allowed)
__device__ float g_xd[(size_t)N_NODES * FEATS];
__device__ float g_agg[(size_t)N_NODES * FEATS];

// ---------------------------------------------------------------------------
// Kernel 1: dropout, JAX *partitionable* threefry-2x32-20 stream.
// Per element i: counter = (hi32(i), lo32(i)) = (0, i); key = (0, 42);
// out32 = y0 ^ y1 ; u = bitcast((out32>>9)|0x3f800000) - 1 ; keep = u < 0.9.
// ---------------------------------------------------------------------------
__device__ __forceinline__ unsigned rotl32(unsigned x, int d) {
    return (x << d) | (x >> (32 - d));
}

__device__ __forceinline__ unsigned threefry_elem(unsigned i) {
    const unsigned ks0 = 0u;
    const unsigned ks1 = 42u;
    const unsigned ks2 = ks0 ^ ks1 ^ 0x1BD11BDAu;

    unsigned x0 = 0u;       // hi word of 64-bit counter
    unsigned x1 = i;        // lo word

    x0 += ks0; x1 += ks1;
#define TF_ROUND(r) { x0 += x1; x1 = rotl32(x1, (r)); x1 ^= x0; }
    TF_ROUND(13) TF_ROUND(15) TF_ROUND(26) TF_ROUND(6)
    x0 += ks1; x1 += ks2 + 1u;
    TF_ROUND(17) TF_ROUND(29) TF_ROUND(16) TF_ROUND(24)
    x0 += ks2; x1 += ks0 + 2u;
    TF_ROUND(13) TF_ROUND(15) TF_ROUND(26) TF_ROUND(6)
    x0 += ks0; x1 += ks1 + 3u;
    TF_ROUND(17) TF_ROUND(29) TF_ROUND(16) TF_ROUND(24)
    x0 += ks1; x1 += ks2 + 4u;
    TF_ROUND(13) TF_ROUND(15) TF_ROUND(26) TF_ROUND(6)
    x0 += ks2; x1 += ks0 + 5u;
#undef TF_ROUND

    return x0 ^ x1;
}

__global__ void dropout_kernel(const float* __restrict__ x) {
    const unsigned base = (blockIdx.x * blockDim.x + threadIdx.x) * 4u;
    if (base >= (unsigned)N_ELEMS) return;

    const float4 v = *reinterpret_cast<const float4*>(x + base);
    const float inv_keep = 1.0f / 0.9f;

    unsigned b0 = threefry_elem(base + 0u);
    unsigned b1 = threefry_elem(base + 1u);
    unsigned b2 = threefry_elem(base + 2u);
    unsigned b3 = threefry_elem(base + 3u);

    float u0 = __uint_as_float((b0 >> 9) | 0x3f800000u) - 1.0f;
    float u1 = __uint_as_float((b1 >> 9) | 0x3f800000u) - 1.0f;
    float u2 = __uint_as_float((b2 >> 9) | 0x3f800000u) - 1.0f;
    float u3 = __uint_as_float((b3 >> 9) | 0x3f800000u) - 1.0f;

    float4 o;
    o.x = (u0 < 0.9f) ? v.x * inv_keep : 0.0f;
    o.y = (u1 < 0.9f) ? v.y * inv_keep : 0.0f;
    o.z = (u2 < 0.9f) ? v.z * inv_keep : 0.0f;
    o.w = (u3 < 0.9f) ? v.w * inv_keep : 0.0f;
    *reinterpret_cast<float4*>(g_xd + base) = o;
}

// ---------------------------------------------------------------------------
// Kernel 2: segment-sum aggregation. edge_dst is sorted; one CTA per dst node,
// binary-search the edge range, reduce in registers. 128 thr x float4 = 512.
// ---------------------------------------------------------------------------
__global__ void agg_kernel(const float* __restrict__ edge_w,
                           const int*   __restrict__ edge_src,
                           const int*   __restrict__ edge_dst) {
    const int node = blockIdx.x;

    int lo = 0, hi = N_EDGES;
    while (lo < hi) { int m = (lo + hi) >> 1; if (edge_dst[m] < node) lo = m + 1; else hi = m; }
    const int start = lo;
    hi = N_EDGES;
    while (lo < hi) { int m = (lo + hi) >> 1; if (edge_dst[m] < node + 1) lo = m + 1; else hi = m; }
    const int end = lo;

    const int f = threadIdx.x;  // 0..127
    float4 acc = make_float4(0.f, 0.f, 0.f, 0.f);

    for (int e = start; e < end; e++) {
        const float w = edge_w[e];
        const int   s = edge_src[e];
        const float4 v = reinterpret_cast<const float4*>(g_xd + (size_t)s * FEATS)[f];
        acc.x += w * v.x; acc.y += w * v.y; acc.z += w * v.z; acc.w += w * v.w;
    }
    reinterpret_cast<float4*>(g_agg + (size_t)node * FEATS)[f] = acc;
}

// ---------------------------------------------------------------------------
// Kernel 3: out = relu(agg @ W + b). M=50000, N=K=512 fp32 SIMT GEMM.
// 128x128 block tile, BK=8, 256 threads, 8x8 microtile.
// ---------------------------------------------------------------------------
__global__ __launch_bounds__(256, 1)
void gemm_bias_relu(const float* __restrict__ W,
                    const float* __restrict__ bias,
                    float* __restrict__ out) {
    const int BM = 128, BN = 128, BK = 8, TM = 8, TN = 8;
    __shared__ float As[BK][BM];
    __shared__ float Bs[BK][BN + 4];

    const int bm = blockIdx.y * BM;
    const int bn = blockIdx.x * BN;
    const int tid = threadIdx.x;
    const int tr = tid >> 4;
    const int tc = tid & 15;

    float acc[TM][TN];
#pragma unroll
    for (int i = 0; i < TM; i++)
#pragma unroll
        for (int j = 0; j < TN; j++) acc[i][j] = 0.f;

    const int laRow = tid >> 1;
    const int laCol = (tid & 1) * 4;
    const int lbK   = tid >> 5;
    const int lbN   = (tid & 31) * 4;

    for (int k0 = 0; k0 < 512; k0 += BK) {
        float4 a4 = make_float4(0.f, 0.f, 0.f, 0.f);
        const int gr = bm + laRow;
        if (gr < N_NODES)
            a4 = *reinterpret_cast<const float4*>(&g_agg[(size_t)gr * 512 + k0 + laCol]);
        As[laCol + 0][laRow] = a4.x;
        As[laCol + 1][laRow] = a4.y;
        As[laCol + 2][laRow] = a4.z;
        As[laCol + 3][laRow] = a4.w;

        const float4 b4 = *reinterpret_cast<const float4*>(&W[(size_t)(k0 + lbK) * 512 + bn + lbN]);
        *reinterpret_cast<float4*>(&Bs[lbK][lbN]) = b4;

        __syncthreads();

#pragma unroll
        for (int kk = 0; kk < BK; kk++) {
            float rm[TM], rn[TN];
#pragma unroll
            for (int i = 0; i < TM; i++) rm[i] = As[kk][tr * TM + i];
#pragma unroll
            for (int j = 0; j < TN; j++) rn[j] = Bs[kk][tc * TN + j];
#pragma unroll
            for (int i = 0; i < TM; i++)
#pragma unroll
                for (int j = 0; j < TN; j++)
                    acc[i][j] = fmaf(rm[i], rn[j], acc[i][j]);
        }
        __syncthreads();
    }

#pragma unroll
    for (int i = 0; i < TM; i++) {
        const int row = bm + tr * TM + i;
        if (row >= N_NODES) continue;
#pragma unroll
        for (int j0 = 0; j0 < TN; j0 += 4) {
            const int col = bn + tc * TN + j0;
            float4 o;
            o.x = fmaxf(acc[i][j0 + 0] + bias[col + 0], 0.f);
            o.y = fmaxf(acc[i][j0 + 1] + bias[col + 1], 0.f);
            o.z = fmaxf(acc[i][j0 + 2] + bias[col + 2], 0.f);
            o.w = fmaxf(acc[i][j0 + 3] + bias[col + 3], 0.f);
            *reinterpret_cast<float4*>(&out[(size_t)row * 512 + col]) = o;
        }
    }
}

// ---------------------------------------------------------------------------
// Launch
// ---------------------------------------------------------------------------
extern "C" void kernel_launch(void* const* d_in, const int* in_sizes, int n_in,
                              void* d_out, int out_size) {
    const float* x        = (const float*)d_in[0];
    const float* edge_w   = (const float*)d_in[1];
    const float* W        = (const float*)d_in[2];
    const float* b        = (const float*)d_in[3];
    const int*   edge_src = (const int*)  d_in[4];
    const int*   edge_dst = (const int*)  d_in[5];
    float* out = (float*)d_out;

    dropout_kernel<<<(N_ELEMS / 4 + 255) / 256, 256>>>(x);
    agg_kernel<<<N_NODES, 128>>>(edge_w, edge_src, edge_dst);
    gemm_bias_relu<<<dim3(512 / 128, (N_NODES + 127) / 128), 256>>>(W, b, out);
}

// round 4
// speedup vs baseline: 2.0130x; 2.0130x over previous
#include <cuda_runtime.h>
#include <cstdint>

#define N_NODES 50000
#define N_EDGES 800000
#define FEATS   512
#define N_ELEMS (N_NODES * FEATS)
#define M_TILES 391                 // ceil(50000/128)
#define PAD_ROWS (M_TILES * 128)    // 50048

// Scratch (device globals — no cudaMalloc allowed). Zero-initialized at load;
// pad rows of g_agg are never written, so they stay zero.
__device__ float g_xd [(size_t)N_NODES * FEATS];
__device__ float g_agg[(size_t)PAD_ROWS * FEATS];
__device__ float g_Wt [(size_t)FEATS * FEATS];      // W^T, tf32-rounded: Wt[n][k]

// ---------------------------------------------------------------------------
// helpers
// ---------------------------------------------------------------------------
__device__ __forceinline__ uint32_t smem_u32(const void* p) {
    uint32_t a;
    asm("{ .reg .u64 t; cvta.to.shared.u64 t, %1; cvt.u32.u64 %0, t; }" : "=r"(a) : "l"(p));
    return a;
}
__device__ __forceinline__ void cp_async16(uint32_t dst, const void* src) {
    asm volatile("cp.async.cg.shared.global [%0], [%1], 16;" :: "r"(dst), "l"(src));
}
__device__ __forceinline__ void cp_commit() {
    asm volatile("cp.async.commit_group;" ::: "memory");
}
template <int N>
__device__ __forceinline__ void cp_wait() {
    asm volatile("cp.async.wait_group %0;" :: "n"(N) : "memory");
}
__device__ __forceinline__ float tf32_rn(float v) {
    uint32_t r;
    asm("cvt.rn.tf32.f32 %0, %1;" : "=r"(r) : "f"(v));
    return __uint_as_float(r);
}
// D = A(16x8 tf32, row) * B(8x8 tf32, col) + D, fp32 accum
__device__ __forceinline__ void mma_tf32(float* c, const uint32_t* a, const uint32_t* b) {
    asm volatile(
        "mma.sync.aligned.m16n8k8.row.col.f32.tf32.tf32.f32 "
        "{%0,%1,%2,%3}, {%4,%5,%6,%7}, {%8,%9}, {%0,%1,%2,%3};"
        : "+f"(c[0]), "+f"(c[1]), "+f"(c[2]), "+f"(c[3])
        : "r"(a[0]), "r"(a[1]), "r"(a[2]), "r"(a[3]), "r"(b[0]), "r"(b[1]));
}

// ---------------------------------------------------------------------------
// Kernel 0: Wt[n][k] = tf32_rn(W[k][n])
// ---------------------------------------------------------------------------
__global__ void transpose_W_kernel(const float* __restrict__ W) {
    __shared__ float t[32][33];
    const int tx = threadIdx.x, ty = threadIdx.y;          // 32 x 8
    const int bx = blockIdx.x, by = blockIdx.y;
    const int x = bx * 32 + tx;
#pragma unroll
    for (int i = 0; i < 4; i++) {
        const int y = by * 32 + ty + i * 8;
        t[ty + i * 8][tx] = W[(size_t)y * 512 + x];
    }
    __syncthreads();
    const int x2 = by * 32 + tx;                           // k
#pragma unroll
    for (int i = 0; i < 4; i++) {
        const int y2 = bx * 32 + ty + i * 8;               // n
        g_Wt[(size_t)y2 * 512 + x2] = tf32_rn(t[tx][ty + i * 8]);
    }
}

// ---------------------------------------------------------------------------
// Kernel 1: dropout, JAX partitionable threefry-2x32-20.
// ---------------------------------------------------------------------------
__device__ __forceinline__ unsigned rotl32(unsigned x, int d) {
    return (x << d) | (x >> (32 - d));
}
__device__ __forceinline__ unsigned threefry_elem(unsigned i) {
    const unsigned ks0 = 0u, ks1 = 42u;
    const unsigned ks2 = ks0 ^ ks1 ^ 0x1BD11BDAu;
    unsigned x0 = 0u, x1 = i;
    x0 += ks0; x1 += ks1;
#define TF_ROUND(r) { x0 += x1; x1 = rotl32(x1, (r)); x1 ^= x0; }
    TF_ROUND(13) TF_ROUND(15) TF_ROUND(26) TF_ROUND(6)
    x0 += ks1; x1 += ks2 + 1u;
    TF_ROUND(17) TF_ROUND(29) TF_ROUND(16) TF_ROUND(24)
    x0 += ks2; x1 += ks0 + 2u;
    TF_ROUND(13) TF_ROUND(15) TF_ROUND(26) TF_ROUND(6)
    x0 += ks0; x1 += ks1 + 3u;
    TF_ROUND(17) TF_ROUND(29) TF_ROUND(16) TF_ROUND(24)
    x0 += ks1; x1 += ks2 + 4u;
    TF_ROUND(13) TF_ROUND(15) TF_ROUND(26) TF_ROUND(6)
    x0 += ks2; x1 += ks0 + 5u;
#undef TF_ROUND
    return x0 ^ x1;
}

__global__ void dropout_kernel(const float* __restrict__ x) {
    const unsigned base = (blockIdx.x * blockDim.x + threadIdx.x) * 4u;
    if (base >= (unsigned)N_ELEMS) return;
    const float4 v = *reinterpret_cast<const float4*>(x + base);
    const float inv_keep = 1.0f / 0.9f;
    unsigned b0 = threefry_elem(base + 0u);
    unsigned b1 = threefry_elem(base + 1u);
    unsigned b2 = threefry_elem(base + 2u);
    unsigned b3 = threefry_elem(base + 3u);
    float u0 = __uint_as_float((b0 >> 9) | 0x3f800000u) - 1.0f;
    float u1 = __uint_as_float((b1 >> 9) | 0x3f800000u) - 1.0f;
    float u2 = __uint_as_float((b2 >> 9) | 0x3f800000u) - 1.0f;
    float u3 = __uint_as_float((b3 >> 9) | 0x3f800000u) - 1.0f;
    float4 o;
    o.x = (u0 < 0.9f) ? v.x * inv_keep : 0.0f;
    o.y = (u1 < 0.9f) ? v.y * inv_keep : 0.0f;
    o.z = (u2 < 0.9f) ? v.z * inv_keep : 0.0f;
    o.w = (u3 < 0.9f) ? v.w * inv_keep : 0.0f;
    *reinterpret_cast<float4*>(g_xd + base) = o;
}

// ---------------------------------------------------------------------------
// Kernel 2: segment-sum aggregation (sorted edge_dst). tf32-round result.
// ---------------------------------------------------------------------------
__global__ void agg_kernel(const float* __restrict__ edge_w,
                           const int*   __restrict__ edge_src,
                           const int*   __restrict__ edge_dst) {
    const int node = blockIdx.x;
    int lo = 0, hi = N_EDGES;
    while (lo < hi) { int m = (lo + hi) >> 1; if (edge_dst[m] < node) lo = m + 1; else hi = m; }
    const int start = lo;
    hi = N_EDGES;
    while (lo < hi) { int m = (lo + hi) >> 1; if (edge_dst[m] < node + 1) lo = m + 1; else hi = m; }
    const int end = lo;

    const int f = threadIdx.x;
    float4 acc = make_float4(0.f, 0.f, 0.f, 0.f);
    for (int e = start; e < end; e++) {
        const float w = edge_w[e];
        const int   s = edge_src[e];
        const float4 v = reinterpret_cast<const float4*>(g_xd + (size_t)s * FEATS)[f];
        acc.x += w * v.x; acc.y += w * v.y; acc.z += w * v.z; acc.w += w * v.w;
    }
    float4 r;
    r.x = tf32_rn(acc.x); r.y = tf32_rn(acc.y); r.z = tf32_rn(acc.z); r.w = tf32_rn(acc.w);
    reinterpret_cast<float4*>(g_agg + (size_t)node * FEATS)[f] = r;
}

// ---------------------------------------------------------------------------
// Kernel 3: mma.sync tf32 GEMM. out = relu(agg @ Wt^T + b).
// 128x128 CTA tile, BK=32, 8 warps (64x32 warp tiles), 2-stage cp.async.
// Smem rows padded to 36 floats -> fragment LDS bank = lane id (conflict-free).
// ---------------------------------------------------------------------------
#define BK 32
#define LDP 36   // padded row stride (floats)

__global__ void __launch_bounds__(256, 2)
gemm_mma_kernel(const float* __restrict__ bias, float* __restrict__ out) {
    __shared__ float As[2][128][LDP];
    __shared__ float Bs[2][128][LDP];

    const int tid   = threadIdx.x;
    const int wid   = tid >> 5;
    const int lane  = tid & 31;
    const int warpM = wid & 1;          // 0..1 -> M offset 0/64
    const int warpN = wid >> 1;         // 0..3 -> N offset 0/32/64/96
    const int m0 = blockIdx.y * 128;
    const int n0 = blockIdx.x * 128;

    const uint32_t aBase = smem_u32(&As[0][0][0]);
    const uint32_t bBase = smem_u32(&Bs[0][0][0]);
    const uint32_t stageBytes = 128 * LDP * 4;

    float acc[4][4][4];
#pragma unroll
    for (int i = 0; i < 4; i++)
#pragma unroll
        for (int j = 0; j < 4; j++)
#pragma unroll
            for (int r = 0; r < 4; r++) acc[i][j][r] = 0.f;

    // global->smem loader for one K chunk
    auto load_tile = [&](int s, int k0) {
#pragma unroll
        for (int it = 0; it < 4; it++) {
            const int idx = it * 256 + tid;            // 0..1023
            const int row = idx >> 3, seg = idx & 7;   // 8 float4 per 32-f row
            cp_async16(aBase + s * stageBytes + (row * LDP + seg * 4) * 4,
                       &g_agg[(size_t)(m0 + row) * 512 + k0 + seg * 4]);
        }
#pragma unroll
        for (int it = 0; it < 4; it++) {
            const int idx = it * 256 + tid;
            const int row = idx >> 3, seg = idx & 7;
            cp_async16(bBase + s * stageBytes + (row * LDP + seg * 4) * 4,
                       &g_Wt[(size_t)(n0 + row) * 512 + k0 + seg * 4]);
        }
        cp_commit();
    };

    load_tile(0, 0);

    const int qrow = lane >> 2;   // 0..7
    const int qcol = lane & 3;    // 0..3

    for (int c = 0; c < 16; c++) {
        const int s = c & 1;
        if (c + 1 < 16) { load_tile(s ^ 1, (c + 1) * BK); cp_wait<1>(); }
        else            { cp_wait<0>(); }
        __syncthreads();

#pragma unroll
        for (int kk = 0; kk < 4; kk++) {
            const int kb = kk * 8;
            uint32_t af[4][4];
#pragma unroll
            for (int mt = 0; mt < 4; mt++) {
                const int r0 = warpM * 64 + mt * 16 + qrow;
                af[mt][0] = __float_as_uint(As[s][r0    ][kb + qcol]);
                af[mt][1] = __float_as_uint(As[s][r0 + 8][kb + qcol]);
                af[mt][2] = __float_as_uint(As[s][r0    ][kb + 4 + qcol]);
                af[mt][3] = __float_as_uint(As[s][r0 + 8][kb + 4 + qcol]);
            }
            uint32_t bf[4][2];
#pragma unroll
            for (int nt = 0; nt < 4; nt++) {
                const int rn = warpN * 32 + nt * 8 + qrow;
                bf[nt][0] = __float_as_uint(Bs[s][rn][kb + qcol]);
                bf[nt][1] = __float_as_uint(Bs[s][rn][kb + 4 + qcol]);
            }
#pragma unroll
            for (int mt = 0; mt < 4; mt++)
#pragma unroll
                for (int nt = 0; nt < 4; nt++)
                    mma_tf32(acc[mt][nt], af[mt], bf[nt]);
        }
        __syncthreads();
    }

    // epilogue: bias + relu
#pragma unroll
    for (int mt = 0; mt < 4; mt++) {
        const int row0 = m0 + warpM * 64 + mt * 16 + qrow;
        const int row1 = row0 + 8;
#pragma unroll
        for (int nt = 0; nt < 4; nt++) {
            const int col = n0 + warpN * 32 + nt * 8 + 2 * qcol;
            const float b0 = __ldg(bias + col);
            const float b1 = __ldg(bias + col + 1);
            if (row0 < N_NODES) {
                float2 o;
                o.x = fmaxf(acc[mt][nt][0] + b0, 0.f);
                o.y = fmaxf(acc[mt][nt][1] + b1, 0.f);
                *reinterpret_cast<float2*>(out + (size_t)row0 * 512 + col) = o;
            }
            if (row1 < N_NODES) {
                float2 o;
                o.x = fmaxf(acc[mt][nt][2] + b0, 0.f);
                o.y = fmaxf(acc[mt][nt][3] + b1, 0.f);
                *reinterpret_cast<float2*>(out + (size_t)row1 * 512 + col) = o;
            }
        }
    }
}

// ---------------------------------------------------------------------------
// Launch
// ---------------------------------------------------------------------------
extern "C" void kernel_launch(void* const* d_in, const int* in_sizes, int n_in,
                              void* d_out, int out_size) {
    const float* x        = (const float*)d_in[0];
    const float* edge_w   = (const float*)d_in[1];
    const float* W        = (const float*)d_in[2];
    const float* b        = (const float*)d_in[3];
    const int*   edge_src = (const int*)  d_in[4];
    const int*   edge_dst = (const int*)  d_in[5];
    float* out = (float*)d_out;

    transpose_W_kernel<<<dim3(16, 16), dim3(32, 8)>>>(W);
    dropout_kernel<<<(N_ELEMS / 4 + 255) / 256, 256>>>(x);
    agg_kernel<<<N_NODES, 128>>>(edge_w, edge_src, edge_dst);
    gemm_mma_kernel<<<dim3(4, M_TILES), 256>>>(b, out);
}

// round 5
// speedup vs baseline: 2.5881x; 1.2857x over previous
#include <cuda_runtime.h>
#include <cstdint>

#define N_NODES 50000
#define N_EDGES 800000
#define FEATS   512
#define N_ELEMS (N_NODES * FEATS)
#define M_TILES 391                 // ceil(50000/128)
#define PAD_ROWS (M_TILES * 128)    // 50048

// Scratch (device globals — no cudaMalloc allowed). Zero-initialized at load;
// pad rows of g_agg are never written, so they stay zero.
__device__ float g_xd [(size_t)N_NODES * FEATS];
__device__ float g_agg[(size_t)PAD_ROWS * FEATS];
__device__ float g_Wt [(size_t)FEATS * FEATS];      // W^T, tf32-rounded: Wt[n][k]
__device__ int   g_rowptr[N_NODES + 1];

// ---------------------------------------------------------------------------
// helpers
// ---------------------------------------------------------------------------
__device__ __forceinline__ uint32_t smem_u32(const void* p) {
    uint32_t a;
    asm("{ .reg .u64 t; cvta.to.shared.u64 t, %1; cvt.u32.u64 %0, t; }" : "=r"(a) : "l"(p));
    return a;
}
__device__ __forceinline__ void cp_async16(uint32_t dst, const void* src) {
    asm volatile("cp.async.cg.shared.global [%0], [%1], 16;" :: "r"(dst), "l"(src));
}
__device__ __forceinline__ void cp_commit() {
    asm volatile("cp.async.commit_group;" ::: "memory");
}
template <int N>
__device__ __forceinline__ void cp_wait() {
    asm volatile("cp.async.wait_group %0;" :: "n"(N) : "memory");
}
__device__ __forceinline__ float tf32_rn(float v) {
    uint32_t r;
    asm("cvt.rn.tf32.f32 %0, %1;" : "=r"(r) : "f"(v));
    return __uint_as_float(r);
}
// D = A(16x8 tf32, row) * B(8x8 tf32, col) + D, fp32 accum
__device__ __forceinline__ void mma_tf32(float* c, const uint32_t* a, const uint32_t* b) {
    asm volatile(
        "mma.sync.aligned.m16n8k8.row.col.f32.tf32.tf32.f32 "
        "{%0,%1,%2,%3}, {%4,%5,%6,%7}, {%8,%9}, {%0,%1,%2,%3};"
        : "+f"(c[0]), "+f"(c[1]), "+f"(c[2]), "+f"(c[3])
        : "r"(a[0]), "r"(a[1]), "r"(a[2]), "r"(a[3]), "r"(b[0]), "r"(b[1]));
}

// ---------------------------------------------------------------------------
// Kernel 0a: Wt[n][k] = tf32_rn(W[k][n])
// ---------------------------------------------------------------------------
__global__ void transpose_W_kernel(const float* __restrict__ W) {
    __shared__ float t[32][33];
    const int tx = threadIdx.x, ty = threadIdx.y;          // 32 x 8
    const int bx = blockIdx.x, by = blockIdx.y;
    const int x = bx * 32 + tx;
#pragma unroll
    for (int i = 0; i < 4; i++) {
        const int y = by * 32 + ty + i * 8;
        t[ty + i * 8][tx] = W[(size_t)y * 512 + x];
    }
    __syncthreads();
    const int x2 = by * 32 + tx;                           // k
#pragma unroll
    for (int i = 0; i < 4; i++) {
        const int y2 = bx * 32 + ty + i * 8;               // n
        g_Wt[(size_t)y2 * 512 + x2] = tf32_rn(t[tx][ty + i * 8]);
    }
}

// ---------------------------------------------------------------------------
// Kernel 0b: row_ptr from sorted edge_dst. row_ptr[n] = first e with dst >= n.
// ---------------------------------------------------------------------------
__global__ void rowptr_kernel(const int* __restrict__ edge_dst) {
    const int e = blockIdx.x * blockDim.x + threadIdx.x;
    if (e > N_EDGES) return;
    const int d_prev = (e == 0)       ? -1      : edge_dst[e - 1];
    const int d_cur  = (e == N_EDGES) ? N_NODES : edge_dst[e];
    for (int n = d_prev + 1; n <= d_cur; n++) g_rowptr[n] = e;
}

// ---------------------------------------------------------------------------
// Kernel 1: dropout, JAX partitionable threefry-2x32-20.
// ---------------------------------------------------------------------------
__device__ __forceinline__ unsigned rotl32(unsigned x, int d) {
    return (x << d) | (x >> (32 - d));
}
__device__ __forceinline__ unsigned threefry_elem(unsigned i) {
    const unsigned ks0 = 0u, ks1 = 42u;
    const unsigned ks2 = ks0 ^ ks1 ^ 0x1BD11BDAu;
    unsigned x0 = 0u, x1 = i;
    x0 += ks0; x1 += ks1;
#define TF_ROUND(r) { x0 += x1; x1 = rotl32(x1, (r)); x1 ^= x0; }
    TF_ROUND(13) TF_ROUND(15) TF_ROUND(26) TF_ROUND(6)
    x0 += ks1; x1 += ks2 + 1u;
    TF_ROUND(17) TF_ROUND(29) TF_ROUND(16) TF_ROUND(24)
    x0 += ks2; x1 += ks0 + 2u;
    TF_ROUND(13) TF_ROUND(15) TF_ROUND(26) TF_ROUND(6)
    x0 += ks0; x1 += ks1 + 3u;
    TF_ROUND(17) TF_ROUND(29) TF_ROUND(16) TF_ROUND(24)
    x0 += ks1; x1 += ks2 + 4u;
    TF_ROUND(13) TF_ROUND(15) TF_ROUND(26) TF_ROUND(6)
    x0 += ks2; x1 += ks0 + 5u;
#undef TF_ROUND
    return x0 ^ x1;
}

__global__ void dropout_kernel(const float* __restrict__ x) {
    const unsigned base = (blockIdx.x * blockDim.x + threadIdx.x) * 4u;
    if (base >= (unsigned)N_ELEMS) return;
    const float4 v = *reinterpret_cast<const float4*>(x + base);
    const float inv_keep = 1.0f / 0.9f;
    unsigned b0 = threefry_elem(base + 0u);
    unsigned b1 = threefry_elem(base + 1u);
    unsigned b2 = threefry_elem(base + 2u);
    unsigned b3 = threefry_elem(base + 3u);
    float u0 = __uint_as_float((b0 >> 9) | 0x3f800000u) - 1.0f;
    float u1 = __uint_as_float((b1 >> 9) | 0x3f800000u) - 1.0f;
    float u2 = __uint_as_float((b2 >> 9) | 0x3f800000u) - 1.0f;
    float u3 = __uint_as_float((b3 >> 9) | 0x3f800000u) - 1.0f;
    float4 o;
    o.x = (u0 < 0.9f) ? v.x * inv_keep : 0.0f;
    o.y = (u1 < 0.9f) ? v.y * inv_keep : 0.0f;
    o.z = (u2 < 0.9f) ? v.z * inv_keep : 0.0f;
    o.w = (u3 < 0.9f) ? v.w * inv_keep : 0.0f;
    *reinterpret_cast<float4*>(g_xd + base) = o;
}

// ---------------------------------------------------------------------------
// Kernel 2: segment-sum aggregation, row_ptr ranges, edge loop unrolled x4
// for MLP. tf32-round result.
// ---------------------------------------------------------------------------
__global__ void agg_kernel(const float* __restrict__ edge_w,
                           const int*   __restrict__ edge_src) {
    const int node = blockIdx.x;
    const int start = g_rowptr[node];
    const int end   = g_rowptr[node + 1];

    const int f = threadIdx.x;
    float4 acc = make_float4(0.f, 0.f, 0.f, 0.f);

    int e = start;
#pragma unroll 1
    for (; e + 4 <= end; e += 4) {
        const float w0 = edge_w[e + 0], w1 = edge_w[e + 1];
        const float w2 = edge_w[e + 2], w3 = edge_w[e + 3];
        const int   s0 = edge_src[e + 0], s1 = edge_src[e + 1];
        const int   s2 = edge_src[e + 2], s3 = edge_src[e + 3];
        const float4 v0 = reinterpret_cast<const float4*>(g_xd + (size_t)s0 * FEATS)[f];
        const float4 v1 = reinterpret_cast<const float4*>(g_xd + (size_t)s1 * FEATS)[f];
        const float4 v2 = reinterpret_cast<const float4*>(g_xd + (size_t)s2 * FEATS)[f];
        const float4 v3 = reinterpret_cast<const float4*>(g_xd + (size_t)s3 * FEATS)[f];
        acc.x += w0 * v0.x + w1 * v1.x + w2 * v2.x + w3 * v3.x;
        acc.y += w0 * v0.y + w1 * v1.y + w2 * v2.y + w3 * v3.y;
        acc.z += w0 * v0.z + w1 * v1.z + w2 * v2.z + w3 * v3.z;
        acc.w += w0 * v0.w + w1 * v1.w + w2 * v2.w + w3 * v3.w;
    }
#pragma unroll 1
    for (; e < end; e++) {
        const float w = edge_w[e];
        const int   s = edge_src[e];
        const float4 v = reinterpret_cast<const float4*>(g_xd + (size_t)s * FEATS)[f];
        acc.x += w * v.x; acc.y += w * v.y; acc.z += w * v.z; acc.w += w * v.w;
    }
    float4 r;
    r.x = tf32_rn(acc.x); r.y = tf32_rn(acc.y); r.z = tf32_rn(acc.z); r.w = tf32_rn(acc.w);
    reinterpret_cast<float4*>(g_agg + (size_t)node * FEATS)[f] = r;
}

// ---------------------------------------------------------------------------
// Kernel 3: mma.sync tf32 GEMM. out = relu(agg @ Wt^T + b).
// 128x128 CTA tile, BK=32, 8 warps (64x32 warp tiles), 2-stage cp.async,
// ONE barrier per K-iter (mma(c-1) precedes iter-c sync in program order,
// so writing the other stage after the sync is race-free).
// ---------------------------------------------------------------------------
#define BK 32
#define LDP 36   // padded row stride (floats)

__global__ void __launch_bounds__(256, 2)
gemm_mma_kernel(const float* __restrict__ bias, float* __restrict__ out) {
    __shared__ float As[2][128][LDP];
    __shared__ float Bs[2][128][LDP];

    const int tid   = threadIdx.x;
    const int wid   = tid >> 5;
    const int lane  = tid & 31;
    const int warpM = wid & 1;          // 0..1 -> M offset 0/64
    const int warpN = wid >> 1;         // 0..3 -> N offset 0/32/64/96
    const int m0 = blockIdx.y * 128;
    const int n0 = blockIdx.x * 128;

    const uint32_t aBase = smem_u32(&As[0][0][0]);
    const uint32_t bBase = smem_u32(&Bs[0][0][0]);
    const uint32_t stageBytes = 128 * LDP * 4;

    float acc[4][4][4];
#pragma unroll
    for (int i = 0; i < 4; i++)
#pragma unroll
        for (int j = 0; j < 4; j++)
#pragma unroll
            for (int r = 0; r < 4; r++) acc[i][j][r] = 0.f;

    auto load_tile = [&](int s, int k0) {
#pragma unroll
        for (int it = 0; it < 4; it++) {
            const int idx = it * 256 + tid;            // 0..1023
            const int row = idx >> 3, seg = idx & 7;
            cp_async16(aBase + s * stageBytes + (row * LDP + seg * 4) * 4,
                       &g_agg[(size_t)(m0 + row) * 512 + k0 + seg * 4]);
        }
#pragma unroll
        for (int it = 0; it < 4; it++) {
            const int idx = it * 256 + tid;
            const int row = idx >> 3, seg = idx & 7;
            cp_async16(bBase + s * stageBytes + (row * LDP + seg * 4) * 4,
                       &g_Wt[(size_t)(n0 + row) * 512 + k0 + seg * 4]);
        }
        cp_commit();
    };

    load_tile(0, 0);

    const int qrow = lane >> 2;   // 0..7
    const int qcol = lane & 3;    // 0..3

    for (int c = 0; c < 16; c++) {
        const int s = c & 1;
        cp_wait<0>();
        __syncthreads();
        if (c + 1 < 16) load_tile(s ^ 1, (c + 1) * BK);   // overlaps mma below

#pragma unroll
        for (int kk = 0; kk < 4; kk++) {
            const int kb = kk * 8;
            uint32_t af[4][4];
#pragma unroll
            for (int mt = 0; mt < 4; mt++) {
                const int r0 = warpM * 64 + mt * 16 + qrow;
                af[mt][0] = __float_as_uint(As[s][r0    ][kb + qcol]);
                af[mt][1] = __float_as_uint(As[s][r0 + 8][kb + qcol]);
                af[mt][2] = __float_as_uint(As[s][r0    ][kb + 4 + qcol]);
                af[mt][3] = __float_as_uint(As[s][r0 + 8][kb + 4 + qcol]);
            }
            uint32_t bf[4][2];
#pragma unroll
            for (int nt = 0; nt < 4; nt++) {
                const int rn = warpN * 32 + nt * 8 + qrow;
                bf[nt][0] = __float_as_uint(Bs[s][rn][kb + qcol]);
                bf[nt][1] = __float_as_uint(Bs[s][rn][kb + 4 + qcol]);
            }
#pragma unroll
            for (int mt = 0; mt < 4; mt++)
#pragma unroll
                for (int nt = 0; nt < 4; nt++)
                    mma_tf32(acc[mt][nt], af[mt], bf[nt]);
        }
    }

    // epilogue: bias + relu
#pragma unroll
    for (int mt = 0; mt < 4; mt++) {
        const int row0 = m0 + warpM * 64 + mt * 16 + qrow;
        const int row1 = row0 + 8;
#pragma unroll
        for (int nt = 0; nt < 4; nt++) {
            const int col = n0 + warpN * 32 + nt * 8 + 2 * qcol;
            const float b0 = __ldg(bias + col);
            const float b1 = __ldg(bias + col + 1);
            if (row0 < N_NODES) {
                float2 o;
                o.x = fmaxf(acc[mt][nt][0] + b0, 0.f);
                o.y = fmaxf(acc[mt][nt][1] + b1, 0.f);
                *reinterpret_cast<float2*>(out + (size_t)row0 * 512 + col) = o;
            }
            if (row1 < N_NODES) {
                float2 o;
                o.x = fmaxf(acc[mt][nt][2] + b0, 0.f);
                o.y = fmaxf(acc[mt][nt][3] + b1, 0.f);
                *reinterpret_cast<float2*>(out + (size_t)row1 * 512 + col) = o;
            }
        }
    }
}

// ---------------------------------------------------------------------------
// Launch
// ---------------------------------------------------------------------------
extern "C" void kernel_launch(void* const* d_in, const int* in_sizes, int n_in,
                              void* d_out, int out_size) {
    const float* x        = (const float*)d_in[0];
    const float* edge_w   = (const float*)d_in[1];
    const float* W        = (const float*)d_in[2];
    const float* b        = (const float*)d_in[3];
    const int*   edge_src = (const int*)  d_in[4];
    const int*   edge_dst = (const int*)  d_in[5];
    float* out = (float*)d_out;

    transpose_W_kernel<<<dim3(16, 16), dim3(32, 8)>>>(W);
    rowptr_kernel<<<(N_EDGES + 256) / 256, 256>>>(edge_dst);
    dropout_kernel<<<(N_ELEMS / 4 + 255) / 256, 256>>>(x);
    agg_kernel<<<N_NODES, 128>>>(edge_w, edge_src);
    gemm_mma_kernel<<<dim3(4, M_TILES), 256>>>(b, out);
}